// round 4
// baseline (speedup 1.0000x reference)
#include <cuda_runtime.h>
#include <cstddef>

#define NB   16
#define HH   512
#define WWID 512
#define NPB  20000
#define NPTS (NB * NPB)        // 320000
#define EPSV 1e-5f
#define NBLK 1250              // NPTS / 256 exactly
#define FBLKS 64
#define FCHUNK 20              // 64*20 >= 1250

// ---------------- scratch ----------------
__device__ int g_map[NB * HH * WWID];                 // 16.8 MB dense index map
__device__ int g_nbr[9 * NPTS];                       // packed (j<<4 | tap), slot-major
__device__ int g_cntv[NPTS];                          // valid-tap count per point
__device__ __align__(16) float g_y1[NPTS * 8];
__device__ __align__(16) float g_y2[NPTS * 16];
__device__ __align__(16) float g_y3[NPTS * 32];
__device__ float g_part[NBLK * 64];                   // per-block [sum|sumsq]
__device__ float g_part2[FBLKS * 64];                 // finalize stage-1 partials
__device__ float g_bn[64];                            // folded scale[0..31], shift[32..63]
__device__ unsigned g_pool[NB * 32];
__device__ unsigned g_fctr[4];                        // finalize last-block counters

// ---------------- init ----------------
__global__ void k_init() {
    int i = blockIdx.x * blockDim.x + threadIdx.x;
    int stride = gridDim.x * blockDim.x;
    int4* m4 = reinterpret_cast<int4*>(g_map);
    const int n4 = NB * HH * WWID / 4;
    int4 neg = make_int4(-1, -1, -1, -1);
    for (int t = i; t < n4; t += stride) m4[t] = neg;
    if (i < NB * 32) g_pool[i] = 0u;
    if (i < 4) g_fctr[i] = 0u;
}

// ---------------- scatter ----------------
__global__ void k_scatter(const int* __restrict__ idx) {
    int i = blockIdx.x * blockDim.x + threadIdx.x;
    if (i < NPTS) {
        int b = idx[3 * i], y = idx[3 * i + 1], x = idx[3 * i + 2];
        g_map[(b << 18) | (y << 9) | x] = i;
    }
}

// ---------------- build neighbor list + fused conv1 (CIN=1, COUT=8) ----------------
__global__ __launch_bounds__(256)
void k_build(const int* __restrict__ idx, const float* __restrict__ feats,
             const float* __restrict__ w1, float* __restrict__ out)
{
    __shared__ float ws[72];
    if (threadIdx.x < 72) ws[threadIdx.x] = w1[threadIdx.x];
    __syncthreads();

    int i = blockIdx.x * 256 + threadIdx.x;
    int b = idx[3 * i], y = idx[3 * i + 1], x = idx[3 * i + 2];
    int base = b << 18;

    // all 9 map loads issued up front (clamped addresses, predicated result) -> MLP=9
    int jj[9];
#pragma unroll
    for (int t = 0; t < 9; t++) {
        int ny = y + t / 3 - 1, nx = x + t % 3 - 1;
        bool ok = ((unsigned)ny < (unsigned)HH) && ((unsigned)nx < (unsigned)WWID);
        int nyc = ok ? ny : y, nxc = ok ? nx : x;
        int j = g_map[base + (nyc << 9) + nxc];
        jj[t] = ok ? j : -1;
    }

    float acc[8];
#pragma unroll
    for (int c = 0; c < 8; c++) acc[c] = 0.f;

    int cnt = 0;
#pragma unroll
    for (int t = 0; t < 9; t++) {
        if (jj[t] >= 0) {
            g_nbr[cnt * NPTS + i] = (jj[t] << 4) | t;
            cnt++;
            float v = feats[jj[t]];
#pragma unroll
            for (int co = 0; co < 8; co++)
                acc[co] = fmaf(v, ws[t * 8 + co], acc[co]);
        }
    }
    g_cntv[i] = cnt;

    float4* orow = reinterpret_cast<float4*>(out + (size_t)i * 8);
#pragma unroll
    for (int c4 = 0; c4 < 2; c4++) {
        float4 o;
        o.x = acc[4 * c4 + 0]; o.y = acc[4 * c4 + 1];
        o.z = acc[4 * c4 + 2]; o.w = acc[4 * c4 + 3];
        orow[c4] = o;
    }

    // block partials (sum | sumsq) for BN1
    int lane = threadIdx.x & 31, wid = threadIdx.x >> 5;
    __shared__ float red[8][64];
#pragma unroll
    for (int co = 0; co < 8; co++) {
        float s = acc[co], q = acc[co] * acc[co];
#pragma unroll
        for (int off = 16; off; off >>= 1) {
            s += __shfl_down_sync(0xffffffffu, s, off);
            q += __shfl_down_sync(0xffffffffu, q, off);
        }
        if (lane == 0) { red[wid][co] = s; red[wid][8 + co] = q; }
    }
    __syncthreads();
    if (threadIdx.x < 16) {
        float t = 0.f;
#pragma unroll
        for (int wdx = 0; wdx < 8; wdx++) t += red[wdx][threadIdx.x];
        g_part[blockIdx.x * 64 + threadIdx.x] = t;
    }
}

// ---------------- conv via neighbor list, fused input BN+ReLU ----------------
template <int CIN, int COUT>
__global__ __launch_bounds__(256)
void k_convN(const float* __restrict__ in, const float* __restrict__ w,
             float* __restrict__ out)
{
    __shared__ float ws[9 * CIN * COUT];
    __shared__ float s_a[CIN], s_b[CIN];
    for (int t = threadIdx.x; t < 9 * CIN * COUT; t += 256) ws[t] = w[t];
    if (threadIdx.x < CIN) {
        s_a[threadIdx.x] = g_bn[threadIdx.x];
        s_b[threadIdx.x] = g_bn[32 + threadIdx.x];
    }
    __syncthreads();

    int i = blockIdx.x * 256 + threadIdx.x;
    int cnt = g_cntv[i];
    float acc[COUT];
#pragma unroll
    for (int c = 0; c < COUT; c++) acc[c] = 0.f;

    for (int s = 0; s < cnt; s++) {
        int p = g_nbr[s * NPTS + i];          // coalesced slot-major read
        int j = p >> 4, t = p & 15;
        const float* wr = &ws[t * (CIN * COUT)];
        const float4* inr = reinterpret_cast<const float4*>(in + (size_t)j * CIN);
#pragma unroll
        for (int c4 = 0; c4 < CIN / 4; c4++) {
            float4 v4 = inr[c4];
            float vv[4] = {v4.x, v4.y, v4.z, v4.w};
#pragma unroll
            for (int u = 0; u < 4; u++) {
                int ci = c4 * 4 + u;
                float v = fmaxf(fmaf(vv[u], s_a[ci], s_b[ci]), 0.f);
#pragma unroll
                for (int co = 0; co < COUT; co++)
                    acc[co] = fmaf(v, wr[ci * COUT + co], acc[co]);
            }
        }
    }

    float4* orow = reinterpret_cast<float4*>(out + (size_t)i * COUT);
#pragma unroll
    for (int c4 = 0; c4 < COUT / 4; c4++) {
        float4 o;
        o.x = acc[4 * c4 + 0]; o.y = acc[4 * c4 + 1];
        o.z = acc[4 * c4 + 2]; o.w = acc[4 * c4 + 3];
        orow[c4] = o;
    }

    int lane = threadIdx.x & 31, wid = threadIdx.x >> 5;
    __shared__ float red[8][64];
#pragma unroll
    for (int co = 0; co < COUT; co++) {
        float s = acc[co], q = acc[co] * acc[co];
#pragma unroll
        for (int off = 16; off; off >>= 1) {
            s += __shfl_down_sync(0xffffffffu, s, off);
            q += __shfl_down_sync(0xffffffffu, q, off);
        }
        if (lane == 0) { red[wid][co] = s; red[wid][COUT + co] = q; }
    }
    __syncthreads();
    if (threadIdx.x < 2 * COUT) {
        float t = 0.f;
#pragma unroll
        for (int wdx = 0; wdx < 8; wdx++) t += red[wdx][threadIdx.x];
        g_part[blockIdx.x * 64 + threadIdx.x] = t;
    }
}

// ---------------- multi-block finalize with deterministic last-block combine ------
__global__ __launch_bounds__(256)
void k_finalize(const float* __restrict__ gamma, const float* __restrict__ beta,
                int cout, int layer)
{
    int c = threadIdx.x & 63, seg = threadIdx.x >> 6;   // 4 segs
    int g = blockIdx.x;
    __shared__ float s[4][64];
    __shared__ bool last;

    int lo = g * FCHUNK;
    int hi = min(lo + FCHUNK, NBLK);
    float a = 0.f;
    for (int blk = lo + seg; blk < hi; blk += 4)
        a += g_part[blk * 64 + c];
    s[seg][c] = a;
    __syncthreads();
    if (threadIdx.x < 64) {
        float t = s[0][threadIdx.x] + s[1][threadIdx.x] + s[2][threadIdx.x] + s[3][threadIdx.x];
        __stcg(&g_part2[g * 64 + threadIdx.x], t);
    }
    __threadfence();
    __syncthreads();
    if (threadIdx.x == 0) {
        unsigned r = atomicAdd(&g_fctr[layer], 1u);
        last = (r == FBLKS - 1);
    }
    __syncthreads();
    if (!last) return;

    // deterministic fixed-order combine of the 64 stage-1 partials
    float a2 = 0.f;
#pragma unroll
    for (int k = 0; k < 16; k++)
        a2 += __ldcg(&g_part2[(seg * 16 + k) * 64 + c]);
    s[seg][c] = a2;
    __syncthreads();
    if (threadIdx.x < 64) {
        float t = s[0][threadIdx.x] + s[1][threadIdx.x] + s[2][threadIdx.x] + s[3][threadIdx.x];
        s[0][threadIdx.x] = t;
    }
    __syncthreads();
    if ((int)threadIdx.x < cout) {
        float m = s[0][threadIdx.x] / (float)NPTS;
        float v = s[0][cout + threadIdx.x] / (float)NPTS - m * m;
        float sc = gamma[threadIdx.x] * rsqrtf(v + EPSV);
        g_bn[threadIdx.x] = sc;
        g_bn[32 + threadIdx.x] = beta[threadIdx.x] - m * sc;
    }
}

// ---------------- BN3+ReLU fused segment-max pool ----------------
__global__ void k_pool(const int* __restrict__ idx) {
    int bb = blockIdx.y;
    int l = blockIdx.x * 256 + threadIdx.x;
    float v[32];
#pragma unroll
    for (int c = 0; c < 32; c++) v[c] = 0.f;
    int myb = -1;
    if (l < NPB) {
        int i = bb * NPB + l;
        myb = idx[3 * i];
        const float4* r = reinterpret_cast<const float4*>(g_y3 + (size_t)i * 32);
#pragma unroll
        for (int c4 = 0; c4 < 8; c4++) {
            float4 t = r[c4];
            float tv[4] = {t.x, t.y, t.z, t.w};
#pragma unroll
            for (int u = 0; u < 4; u++) {
                int c = c4 * 4 + u;
                v[c] = fmaxf(fmaf(tv[u], g_bn[c], g_bn[32 + c]), 0.f);
            }
        }
    }
    if (myb >= 0 && myb != bb) {
#pragma unroll
        for (int c = 0; c < 32; c++) atomicMax(&g_pool[myb * 32 + c], __float_as_uint(v[c]));
#pragma unroll
        for (int c = 0; c < 32; c++) v[c] = 0.f;
    }
    __shared__ float red[8][32];
    int lane = threadIdx.x & 31, wid = threadIdx.x >> 5;
#pragma unroll
    for (int c = 0; c < 32; c++) {
        float m = v[c];
#pragma unroll
        for (int off = 16; off; off >>= 1)
            m = fmaxf(m, __shfl_down_sync(0xffffffffu, m, off));
        if (lane == 0) red[wid][c] = m;
    }
    __syncthreads();
    if (threadIdx.x < 32) {
        float m = 0.f;
#pragma unroll
        for (int wdx = 0; wdx < 8; wdx++) m = fmaxf(m, red[wdx][threadIdx.x]);
        atomicMax(&g_pool[bb * 32 + threadIdx.x], __float_as_uint(m));
    }
}

// ---------------- final FC + ReLU ----------------
__global__ void k_fc(const float* __restrict__ Wfc, const float* __restrict__ bfc,
                     float* __restrict__ out)
{
    int bb = blockIdx.x, co = threadIdx.x;
    __shared__ float p[32];
    if (threadIdx.x < 32) p[threadIdx.x] = __uint_as_float(g_pool[bb * 32 + threadIdx.x]);
    __syncthreads();
    float acc = bfc[co];
#pragma unroll
    for (int ci = 0; ci < 32; ci++)
        acc = fmaf(p[ci], Wfc[ci * 128 + co], acc);
    out[bb * 128 + co] = fmaxf(acc, 0.f);
}

// ---------------- launch ----------------
extern "C" void kernel_launch(void* const* d_in, const int* in_sizes, int n_in,
                              void* d_out, int out_size)
{
    const float* feats = (const float*)d_in[0];
    const int*   idx   = (const int*)d_in[1];
    const float* W1    = (const float*)d_in[2];
    const float* g1    = (const float*)d_in[3];
    const float* b1    = (const float*)d_in[4];
    const float* W2    = (const float*)d_in[5];
    const float* g2    = (const float*)d_in[6];
    const float* b2    = (const float*)d_in[7];
    const float* W3    = (const float*)d_in[8];
    const float* g3    = (const float*)d_in[9];
    const float* b3    = (const float*)d_in[10];
    const float* Wfc   = (const float*)d_in[11];
    const float* bfc   = (const float*)d_in[12];
    float* out = (float*)d_out;

    float *y1, *y2, *y3;
    cudaGetSymbolAddress((void**)&y1, g_y1);
    cudaGetSymbolAddress((void**)&y2, g_y2);
    cudaGetSymbolAddress((void**)&y3, g_y3);

    k_init<<<1024, 256>>>();
    k_scatter<<<NBLK, 256>>>(idx);

    k_build<<<NBLK, 256>>>(idx, feats, W1, y1);
    k_finalize<<<FBLKS, 256>>>(g1, b1, 8, 1);

    k_convN<8, 16><<<NBLK, 256>>>(y1, W2, y2);
    k_finalize<<<FBLKS, 256>>>(g2, b2, 16, 2);

    k_convN<16, 32><<<NBLK, 256>>>(y2, W3, y3);
    k_finalize<<<FBLKS, 256>>>(g3, b3, 32, 3);

    dim3 pg((NPB + 255) / 256, NB);
    k_pool<<<pg, 256>>>(idx);
    k_fc<<<NB, 128>>>(Wfc, bfc, out);
}

// round 5
// speedup vs baseline: 1.0128x; 1.0128x over previous
#include <cuda_runtime.h>
#include <cstddef>

#define NB    16
#define HH    512
#define WWID  512
#define NPB   20000
#define NPTS  (NB * NPB)          // 320000
#define EPSV  1e-5f
#define GRIDB 296
#define BLKT  256
#define NT    (GRIDB * BLKT)      // 75776 threads
#define WT    (GRIDB * 8)         // 2368 warps

// ---------------- scratch (device globals) ----------------
__device__ int g_map[NB * HH * WWID];              // 16.8 MB dense index map
__device__ int g_nbr[9 * NPTS];                    // packed (j<<4 | tap), slot-major
__device__ int g_cntv[NPTS];
__device__ __align__(16) float g_y1[NPTS * 8];
__device__ __align__(16) float g_y2[NPTS * 16];
__device__ __align__(16) float g_y3[NPTS * 32];
__device__ float g_part[GRIDB * 64];               // per-block [sum | sumsq]
__device__ unsigned g_pool[NB * 32];
__device__ unsigned g_barcnt;                      // grid barrier state (persists; self-resetting)
__device__ unsigned g_bargen;

// ---------------- grid barrier (sense-reversal, co-resident grid) ----------------
__device__ __forceinline__ void grid_barrier() {
    __syncthreads();
    __threadfence();
    if (threadIdx.x == 0) {
        unsigned gen = __ldcg(&g_bargen);
        if (atomicAdd(&g_barcnt, 1u) == GRIDB - 1u) {
            atomicExch(&g_barcnt, 0u);
            __threadfence();
            atomicAdd(&g_bargen, 1u);
        } else {
            while (__ldcg(&g_bargen) == gen) __nanosleep(64);
        }
    }
    __syncthreads();
}

// ---------------- per-channel stats sweep: sum & sumsq of y[NPTS*C] ----------------
template <int C>
__device__ __forceinline__ void stats_sweep(const float* __restrict__ y, float* s_red) {
    const int total = NPTS * C;
    const int chunk = ((total + WT * 32 - 1) / (WT * 32)) * 32;   // per-warp, mult of 32
    int warp = threadIdx.x >> 5, lane = threadIdx.x & 31;
    int gwarp = blockIdx.x * 8 + warp;
    int lo = gwarp * chunk;
    int hi = min(lo + chunk, total);
    float s = 0.f, q = 0.f;
#pragma unroll 4
    for (int f = lo + lane; f < hi; f += 32) {
        float v = y[f];
        s += v; q = fmaf(v, v, q);
    }
    if (C <= 8)  { s += __shfl_xor_sync(~0u, s, 8);  q += __shfl_xor_sync(~0u, q, 8); }
    if (C <= 16) { s += __shfl_xor_sync(~0u, s, 16); q += __shfl_xor_sync(~0u, q, 16); }
    if (lane < C) { s_red[warp * 64 + lane] = s; s_red[warp * 64 + C + lane] = q; }
    __syncthreads();
    if (threadIdx.x < 2 * C) {
        float t = 0.f;
#pragma unroll
        for (int w = 0; w < 8; w++) t += s_red[w * 64 + threadIdx.x];
        g_part[blockIdx.x * 64 + threadIdx.x] = t;
    }
    __syncthreads();
}

// ---------------- BN fold (every block, redundantly, into its own smem) ----------------
template <int C>
__device__ __forceinline__ void bn_fold(const float* __restrict__ gamma,
                                        const float* __restrict__ beta,
                                        float* s_ab, float* s4) {
    int c = threadIdx.x & 63, seg = threadIdx.x >> 6;
    float a = 0.f;
    if (c < 2 * C) {
        for (int blk = seg; blk < GRIDB; blk += 4)
            a += __ldcg(&g_part[blk * 64 + c]);
    }
    s4[seg * 64 + c] = a;
    __syncthreads();
    if ((int)threadIdx.x < C) {
        int c0 = threadIdx.x;
        float S = s4[c0] + s4[64 + c0] + s4[128 + c0] + s4[192 + c0];
        float Q = s4[C + c0] + s4[64 + C + c0] + s4[128 + C + c0] + s4[192 + C + c0];
        float m = S / (float)NPTS;
        float var = Q / (float)NPTS - m * m;
        float sc = gamma[c0] * rsqrtf(var + EPSV);
        s_ab[c0] = sc;
        s_ab[32 + c0] = beta[c0] - m * sc;
    }
    __syncthreads();
}

// ---------------- list-driven conv with fused input BN+ReLU ----------------
template <int CIN, int COUT>
__device__ __forceinline__ void convN(const float* __restrict__ in,
                                      const float* __restrict__ w,
                                      float* __restrict__ out,
                                      const float* s_ab, float* s_ws, int gtid) {
    for (int t = threadIdx.x; t < 9 * CIN * COUT; t += BLKT) s_ws[t] = w[t];
    __syncthreads();
    for (int i = gtid; i < NPTS; i += NT) {
        int cnt = g_cntv[i];
        float acc[COUT];
#pragma unroll
        for (int c = 0; c < COUT; c++) acc[c] = 0.f;
        for (int s = 0; s < cnt; s++) {
            int p = g_nbr[s * NPTS + i];
            int j = p >> 4, t = p & 15;
            const float* wr = s_ws + t * (CIN * COUT);
            const float4* inr = reinterpret_cast<const float4*>(in + (size_t)j * CIN);
#pragma unroll
            for (int c4 = 0; c4 < CIN / 4; c4++) {
                float4 v4 = inr[c4];
                float vv[4] = {v4.x, v4.y, v4.z, v4.w};
#pragma unroll
                for (int u = 0; u < 4; u++) {
                    int ci = c4 * 4 + u;
                    float v = fmaxf(fmaf(vv[u], s_ab[ci], s_ab[32 + ci]), 0.f);
#pragma unroll
                    for (int co = 0; co < COUT; co++)
                        acc[co] = fmaf(v, wr[ci * COUT + co], acc[co]);
                }
            }
        }
        float4* orow = reinterpret_cast<float4*>(out + (size_t)i * COUT);
#pragma unroll
        for (int c4 = 0; c4 < COUT / 4; c4++) {
            float4 o;
            o.x = acc[4 * c4 + 0]; o.y = acc[4 * c4 + 1];
            o.z = acc[4 * c4 + 2]; o.w = acc[4 * c4 + 3];
            orow[c4] = o;
        }
    }
}

// ---------------- the whole network in one persistent kernel ----------------
__global__ __launch_bounds__(BLKT, 2)
void mega(const float* __restrict__ feats, const int* __restrict__ idx,
          const float* __restrict__ W1, const float* __restrict__ g1, const float* __restrict__ b1,
          const float* __restrict__ W2, const float* __restrict__ g2, const float* __restrict__ b2,
          const float* __restrict__ W3, const float* __restrict__ g3, const float* __restrict__ b3,
          const float* __restrict__ Wfc, const float* __restrict__ bfc,
          float* __restrict__ out)
{
    __shared__ float s_ws[4608];      // weights (max: conv3 9*16*32)
    __shared__ float s_ab[64];        // folded BN scale[0..31], shift[32..63]
    __shared__ float s_red[8 * 64];   // stats warp partials
    __shared__ float s4[4 * 64];      // fold segments

    int gtid = blockIdx.x * BLKT + threadIdx.x;
    int warp = threadIdx.x >> 5, lane = threadIdx.x & 31;

    // ---- P0: clear map + pool ----
    {
        int4* m4 = reinterpret_cast<int4*>(g_map);
        const int n4 = NB * HH * WWID / 4;
        int4 neg = make_int4(-1, -1, -1, -1);
        for (int t = gtid; t < n4; t += NT) m4[t] = neg;
        if (gtid < NB * 32) g_pool[gtid] = 0u;
    }
    grid_barrier();

    // ---- P1: scatter ----
    for (int i = gtid; i < NPTS; i += NT) {
        int b = idx[3 * i], y = idx[3 * i + 1], x = idx[3 * i + 2];
        g_map[(b << 18) | (y << 9) | x] = i;
    }
    grid_barrier();

    // ---- P2: conv1 (CIN=1) + neighbor-list build ----
    if (threadIdx.x < 72) s_ws[threadIdx.x] = W1[threadIdx.x];
    __syncthreads();
    for (int i = gtid; i < NPTS; i += NT) {
        int b = idx[3 * i], y = idx[3 * i + 1], x = idx[3 * i + 2];
        int base = b << 18;
        int jj[9];
#pragma unroll
        for (int t = 0; t < 9; t++) {
            int ny = y + t / 3 - 1, nx = x + t % 3 - 1;
            bool ok = ((unsigned)ny < (unsigned)HH) && ((unsigned)nx < (unsigned)WWID);
            int nyc = ok ? ny : y, nxc = ok ? nx : x;
            int j = g_map[base + (nyc << 9) + nxc];
            jj[t] = ok ? j : -1;
        }
        float acc[8];
#pragma unroll
        for (int c = 0; c < 8; c++) acc[c] = 0.f;
        int cnt = 0;
#pragma unroll
        for (int t = 0; t < 9; t++) {
            if (jj[t] >= 0) {
                g_nbr[cnt * NPTS + i] = (jj[t] << 4) | t;
                cnt++;
                float v = feats[jj[t]];
#pragma unroll
                for (int co = 0; co < 8; co++)
                    acc[co] = fmaf(v, s_ws[t * 8 + co], acc[co]);
            }
        }
        g_cntv[i] = cnt;
        float4* orow = reinterpret_cast<float4*>(g_y1 + (size_t)i * 8);
        float4 o0 = make_float4(acc[0], acc[1], acc[2], acc[3]);
        float4 o1 = make_float4(acc[4], acc[5], acc[6], acc[7]);
        orow[0] = o0; orow[1] = o1;
    }
    grid_barrier();

    // ---- P3: stats over y1 ----
    stats_sweep<8>(g_y1, s_red);
    grid_barrier();

    // ---- P4: fold BN1 (all blocks) + conv2 ----
    bn_fold<8>(g1, b1, s_ab, s4);
    convN<8, 16>(g_y1, W2, g_y2, s_ab, s_ws, gtid);
    grid_barrier();

    // ---- P5: stats over y2 ----
    stats_sweep<16>(g_y2, s_red);
    grid_barrier();

    // ---- P6: fold BN2 + conv3 ----
    bn_fold<16>(g2, b2, s_ab, s4);
    convN<16, 32>(g_y2, W3, g_y3, s_ab, s_ws, gtid);
    grid_barrier();

    // ---- P7: stats over y3 ----
    stats_sweep<32>(g_y3, s_red);
    grid_barrier();

    // ---- P8: fold BN3 + pooled segment-max (contiguous rows per warp) ----
    bn_fold<32>(g3, b3, s_ab, s4);
    {
        const int RPW = (NPTS + WT - 1) / WT;     // 136 rows per warp
        int gwarp = blockIdx.x * 8 + warp;
        int lo = gwarp * RPW;
        int hi = min(lo + RPW, NPTS);
        float a3 = s_ab[lane], b3v = s_ab[32 + lane];
        int curb = -1;
        float vmax = 0.f;
        for (int r = lo; r < hi; r++) {
            int rb = idx[3 * r];
            if (rb != curb) {
                if (curb >= 0 && lane < 32)
                    atomicMax(&g_pool[curb * 32 + lane], __float_as_uint(vmax));
                curb = rb; vmax = 0.f;
            }
            float v = fmaxf(fmaf(g_y3[(size_t)r * 32 + lane], a3, b3v), 0.f);
            vmax = fmaxf(vmax, v);
        }
        if (curb >= 0)
            atomicMax(&g_pool[curb * 32 + lane], __float_as_uint(vmax));
    }
    grid_barrier();

    // ---- P9: FC + ReLU ----
    if (gtid < NB * 128) {
        int bi = gtid >> 7, co = gtid & 127;
        float acc = bfc[co];
#pragma unroll
        for (int ci = 0; ci < 32; ci++) {
            float p = __uint_as_float(__ldcg(&g_pool[bi * 32 + ci]));
            acc = fmaf(p, Wfc[ci * 128 + co], acc);
        }
        out[bi * 128 + co] = fmaxf(acc, 0.f);
    }
}

// ---------------- launch ----------------
extern "C" void kernel_launch(void* const* d_in, const int* in_sizes, int n_in,
                              void* d_out, int out_size)
{
    const float* feats = (const float*)d_in[0];
    const int*   idx   = (const int*)d_in[1];
    const float* W1    = (const float*)d_in[2];
    const float* g1    = (const float*)d_in[3];
    const float* b1    = (const float*)d_in[4];
    const float* W2    = (const float*)d_in[5];
    const float* g2    = (const float*)d_in[6];
    const float* b2    = (const float*)d_in[7];
    const float* W3    = (const float*)d_in[8];
    const float* g3    = (const float*)d_in[9];
    const float* b3    = (const float*)d_in[10];
    const float* Wfc   = (const float*)d_in[11];
    const float* bfc   = (const float*)d_in[12];
    float* out = (float*)d_out;

    mega<<<GRIDB, BLKT>>>(feats, idx, W1, g1, b1, W2, g2, b2, W3, g3, b3,
                          Wfc, bfc, out);
}